// round 6
// baseline (speedup 1.0000x reference)
#include <cuda_runtime.h>

#define NTOK 4096
#define EDIM 384
#define NH   6
#define HD   64
#define MAXD 20
#define LOG2E 1.4426950408889634f

// Scratch: Q,K stored d-major [h][d][n] (so attention needs no smem transpose);
// V stored token-major [h][n][d].
__device__ float g_Q[NH * HD * NTOK];
__device__ float g_K[NH * HD * NTOK];
__device__ float g_V[NH * NTOK * HD];

// ---------------------------------------------------------------------------
// Packed fp32x2 helpers (Blackwell FFMA2: 2 fp32 MACs per issue)
// ---------------------------------------------------------------------------
__device__ __forceinline__ unsigned long long pack2(float x) {
    unsigned long long r;
    unsigned int u = __float_as_uint(x);
    asm("mov.b64 %0, {%1, %1};" : "=l"(r) : "r"(u));
    return r;
}
__device__ __forceinline__ unsigned long long fma2(
    unsigned long long a, unsigned long long b, unsigned long long c) {
    unsigned long long d;
    asm("fma.rn.f32x2 %0, %1, %2, %3;" : "=l"(d) : "l"(a), "l"(b), "l"(c));
    return d;
}
__device__ __forceinline__ unsigned long long mul2(
    unsigned long long a, unsigned long long b) {
    unsigned long long d;
    asm("mul.rn.f32x2 %0, %1, %2;" : "=l"(d) : "l"(a), "l"(b));
    return d;
}
__device__ __forceinline__ float2 unpack2(unsigned long long v) {
    unsigned int lo, hi;
    asm("mov.b64 {%0, %1}, %2;" : "=r"(lo), "=r"(hi) : "l"(v));
    return make_float2(__uint_as_float(lo), __uint_as_float(hi));
}
__device__ __forceinline__ float ex2(float x) {
    float r;
    asm("ex2.approx.f32 %0, %1;" : "=f"(r) : "f"(x));
    return r;
}
__device__ __forceinline__ void cp_async16(unsigned int dst_smem, const void* src) {
    asm volatile("cp.async.cg.shared.global [%0], [%1], 16;"
                 :: "r"(dst_smem), "l"(src));
}
__device__ __forceinline__ void cp_async_commit() {
    asm volatile("cp.async.commit_group;" ::: "memory");
}
__device__ __forceinline__ void cp_async_wait_all() {
    asm volatile("cp.async.wait_group 0;" ::: "memory");
}

// ---------------------------------------------------------------------------
// Kernel 1: QKV projection, FFMA2 microkernel.
// C[n,c] = sum_k x[n,k]*w[c,k] + b[c].
// Q,K written [h][d][n] (Q pre-scaled by log2e); V written [h][n][d].
// 256 threads, 64x64 tile, frag 4 rows x 4 cols (2 packed col-pairs).
// ---------------------------------------------------------------------------
__global__ __launch_bounds__(256) void qkv_proj_kernel(
    const float* __restrict__ x,
    const float* __restrict__ w,
    const float* __restrict__ b)
{
    __shared__ __align__(16) float Xt[64 * 68];  // [kk][row]
    __shared__ __align__(16) float Wt[64 * 68];  // [kk][col]

    const int tid = threadIdx.x;
    const int tx = tid & 15;
    const int ty = tid >> 4;
    const int r0 = blockIdx.x * 64;
    const int by = blockIdx.y;
    const int c0 = by * 64;
    const int s  = by / NH;              // 0=Q, 1=K, 2=V
    const int h  = by % NH;

    unsigned long long acc2[4][2];       // [row][col-pair]
    #pragma unroll
    for (int i = 0; i < 4; i++) { acc2[i][0] = 0ull; acc2[i][1] = 0ull; }

    for (int k0 = 0; k0 < EDIM; k0 += 64) {
        for (int idx = tid; idx < 4096; idx += 256) {
            int kk = idx & 63;
            int row = idx >> 6;
            Xt[kk * 68 + row] = x[(r0 + row) * EDIM + k0 + kk];
            Wt[kk * 68 + row] = w[(c0 + row) * EDIM + k0 + kk];
        }
        __syncthreads();
        #pragma unroll 8
        for (int kk = 0; kk < 64; kk++) {
            float4 xv = *(const float4*)&Xt[kk * 68 + 4 * ty];
            ulonglong2 wv = *(const ulonglong2*)&Wt[kk * 68 + 4 * tx];
            unsigned long long xd[4];
            xd[0] = pack2(xv.x); xd[1] = pack2(xv.y);
            xd[2] = pack2(xv.z); xd[3] = pack2(xv.w);
            #pragma unroll
            for (int i = 0; i < 4; i++) {
                acc2[i][0] = fma2(xd[i], wv.x, acc2[i][0]);
                acc2[i][1] = fma2(xd[i], wv.y, acc2[i][1]);
            }
        }
        __syncthreads();
    }

    // unpack to scalar 4x4 frag
    float acc[4][4];
    #pragma unroll
    for (int i = 0; i < 4; i++) {
        float2 f0 = unpack2(acc2[i][0]);
        float2 f1 = unpack2(acc2[i][1]);
        acc[i][0] = f0.x; acc[i][1] = f0.y;
        acc[i][2] = f1.x; acc[i][3] = f1.y;
    }

    float4 bv = *(const float4*)&b[c0 + 4 * tx];
    float bf[4] = {bv.x, bv.y, bv.z, bv.w};

    if (s == 2) {
        // V: [h][n][d], float4 along d
        #pragma unroll
        for (int i = 0; i < 4; i++) {
            int n = r0 + 4 * ty + i;
            float4 ov;
            ov.x = acc[i][0] + bf[0];
            ov.y = acc[i][1] + bf[1];
            ov.z = acc[i][2] + bf[2];
            ov.w = acc[i][3] + bf[3];
            *(float4*)&g_V[(h * NTOK + n) * HD + 4 * tx] = ov;
        }
    } else {
        // Q/K: [h][d][n], float4 along n. Q pre-scaled by log2e.
        float* dst = (s == 0) ? g_Q : g_K;
        float scl  = (s == 0) ? LOG2E : 1.0f;
        #pragma unroll
        for (int j = 0; j < 4; j++) {
            int d = 4 * tx + j;
            float4 ov;
            ov.x = (acc[0][j] + bf[j]) * scl;
            ov.y = (acc[1][j] + bf[j]) * scl;
            ov.z = (acc[2][j] + bf[j]) * scl;
            ov.w = (acc[3][j] + bf[j]) * scl;
            *(float4*)&dst[(h * HD + d) * NTOK + r0 + 4 * ty] = ov;
        }
    }
}

// ---------------------------------------------------------------------------
// Kernel 2: flash attention with RPE bias, FFMA2 microkernel,
// cp.async double-buffered K/V pipeline (2 syncs/tile, loads off crit path).
// CTA = (64-query tile, head), 128 threads: tx=tid&7, ty=tid>>3.
// Frags: 4 rows x 8 cols, cols split {4tx..4tx+3} u {32+4tx..35+4tx}.
// Q pre-scaled by log2e in projection; softmax in exp2 domain.
// smem: Qt | K0 | K1 | V0 | V1 | Pt | bias  (each tile buf 64x68 floats)
// ---------------------------------------------------------------------------
#define TB (64 * 68)

__device__ __forceinline__ void prefetch_tile(
    int h, int j0, int tid, unsigned int kdst, unsigned int vdst)
{
    #pragma unroll
    for (int it = 0; it < 8; it++) {
        int idx = tid + it * 128;
        int a  = idx >> 4;               // d-row for K, token-row for V
        int c4 = (idx & 15) * 4;
        unsigned int soff = (unsigned int)(a * 68 + c4) * 4u;
        cp_async16(kdst + soff, &g_K[(h * HD + a) * NTOK + j0 + c4]);
        cp_async16(vdst + soff, &g_V[(h * NTOK + j0 + a) * HD + c4]);
    }
}

__global__ __launch_bounds__(128, 2) void attn_kernel(
    const int*   __restrict__ dist,
    const float* __restrict__ rpe,
    float*       __restrict__ out)
{
    extern __shared__ __align__(16) float smem[];
    float* Qt     = smem;                 // [64][68]  Q^T: [d][row]
    float* Kb     = smem + TB;            // two K^T buffers [d][col]
    float* Vb     = smem + 3 * TB;        // two V buffers [k][d]
    float* Pt     = smem + 5 * TB;        // P^T: [k][row]
    float* bias_s = smem + 6 * TB;        // [21]

    const int tid = threadIdx.x;
    const int tx = tid & 7;
    const int ty = tid >> 3;
    const int h  = blockIdx.y;
    const int q0 = blockIdx.x * 64;

    const unsigned int smem_u32 = (unsigned int)__cvta_generic_to_shared(smem);
    const unsigned int kbuf_u32[2] = {smem_u32 + 1 * TB * 4, smem_u32 + 2 * TB * 4};
    const unsigned int vbuf_u32[2] = {smem_u32 + 3 * TB * 4, smem_u32 + 4 * TB * 4};

    // start async load of tile 0 immediately
    prefetch_tile(h, 0, tid, kbuf_u32[0], vbuf_u32[0]);
    cp_async_commit();

    if (tid < MAXD + 1) bias_s[tid] = rpe[tid * NH + h] * LOG2E;

    // Q tile: g_Q is [h][d][n] -> direct float4 copy rows of d (no transpose)
    for (int idx = tid; idx < 1024; idx += 128) {
        int d  = idx >> 4;
        int c4 = (idx & 15) * 4;
        *(float4*)&Qt[d * 68 + c4] =
            *(const float4*)&g_Q[(h * HD + d) * NTOK + q0 + c4];
    }

    unsigned long long o2[4][4];          // [row][d-pair]; 0,1 -> d 4tx.., 2,3 -> d 32+4tx..
    #pragma unroll
    for (int i = 0; i < 4; i++)
        #pragma unroll
        for (int j = 0; j < 4; j++) o2[i][j] = 0ull;
    float m[4] = {-1e30f, -1e30f, -1e30f, -1e30f};
    float l[4] = {};

    cp_async_wait_all();
    __syncthreads();                      // tile 0, Qt, bias_s all visible

    int cur = 0;
    for (int j0 = 0; j0 < NTOK; j0 += 64) {
        // async prefetch of next tile into the alternate buffer
        int jn = (j0 + 64) & (NTOK - 1);  // last iter wraps to 0 (harmless)
        prefetch_tile(h, jn, tid, kbuf_u32[cur ^ 1], vbuf_u32[cur ^ 1]);
        cp_async_commit();

        const float* KPt = Kb + cur * TB;
        const float* Vs  = Vb + cur * TB;

        // distance rows: issued now, consumed after the S-GEMM
        int4 drow[4][2];
        #pragma unroll
        for (int i = 0; i < 4; i++) {
            const int* dp = &dist[(q0 + 4 * ty + i) * NTOK + j0];
            drow[i][0] = *(const int4*)(dp + 4 * tx);
            drow[i][1] = *(const int4*)(dp + 32 + 4 * tx);
        }

        // S = (log2e*Q) K^T : packed FFMA2, 64 d-steps
        unsigned long long s2[4][4];
        #pragma unroll
        for (int i = 0; i < 4; i++)
            #pragma unroll
            for (int j = 0; j < 4; j++) s2[i][j] = 0ull;

        #pragma unroll 8
        for (int kk = 0; kk < 64; kk++) {
            float4 qv = *(const float4*)&Qt[kk * 68 + 4 * ty];
            ulonglong2 ka = *(const ulonglong2*)&KPt[kk * 68 + 4 * tx];
            ulonglong2 kb = *(const ulonglong2*)&KPt[kk * 68 + 32 + 4 * tx];
            unsigned long long qd[4];
            qd[0] = pack2(qv.x); qd[1] = pack2(qv.y);
            qd[2] = pack2(qv.z); qd[3] = pack2(qv.w);
            #pragma unroll
            for (int i = 0; i < 4; i++) {
                s2[i][0] = fma2(qd[i], ka.x, s2[i][0]);
                s2[i][1] = fma2(qd[i], ka.y, s2[i][1]);
                s2[i][2] = fma2(qd[i], kb.x, s2[i][2]);
                s2[i][3] = fma2(qd[i], kb.y, s2[i][3]);
            }
        }

        // unpack, bias lookup (upper clamp only; distance >= 0 by spec),
        // online softmax over 8 tx lanes
        float p[4][8];
        #pragma unroll
        for (int i = 0; i < 4; i++) {
            int da[8] = {drow[i][0].x, drow[i][0].y, drow[i][0].z, drow[i][0].w,
                         drow[i][1].x, drow[i][1].y, drow[i][1].z, drow[i][1].w};
            float s[8];
            #pragma unroll
            for (int jc = 0; jc < 4; jc++) {
                float2 f = unpack2(s2[i][jc]);
                s[2 * jc]     = f.x;
                s[2 * jc + 1] = f.y;
            }
            #pragma unroll
            for (int j = 0; j < 8; j++) {
                int dc = (da[j] > MAXD) ? MAXD : da[j];
                s[j] += bias_s[dc];
            }
            float mt = s[0];
            #pragma unroll
            for (int j = 1; j < 8; j++) mt = fmaxf(mt, s[j]);
            mt = fmaxf(mt, __shfl_xor_sync(0xffffffffu, mt, 1));
            mt = fmaxf(mt, __shfl_xor_sync(0xffffffffu, mt, 2));
            mt = fmaxf(mt, __shfl_xor_sync(0xffffffffu, mt, 4));
            float mn = fmaxf(m[i], mt);
            float sc = ex2(m[i] - mn);
            float rs = 0.f;
            #pragma unroll
            for (int j = 0; j < 8; j++) {
                p[i][j] = ex2(s[j] - mn);
                rs += p[i][j];
            }
            rs += __shfl_xor_sync(0xffffffffu, rs, 1);
            rs += __shfl_xor_sync(0xffffffffu, rs, 2);
            rs += __shfl_xor_sync(0xffffffffu, rs, 4);
            l[i] = l[i] * sc + rs;
            m[i] = mn;
            unsigned long long sc2 = pack2(sc);
            #pragma unroll
            for (int jc = 0; jc < 4; jc++) o2[i][jc] = mul2(o2[i][jc], sc2);
        }

        // write P^T: [k][row]; k = 4tx+j (j<4) or 32+4tx+(j-4) (j>=4)
        #pragma unroll
        for (int j = 0; j < 8; j++) {
            int k = (j < 4) ? (4 * tx + j) : (32 + 4 * tx + (j - 4));
            float4 pv;
            pv.x = p[0][j]; pv.y = p[1][j]; pv.z = p[2][j]; pv.w = p[3][j];
            *(float4*)&Pt[k * 68 + 4 * ty] = pv;
        }
        __syncthreads();                  // Pt visible to all

        // O += P V : packed FFMA2, 64 k-steps
        #pragma unroll 8
        for (int kk = 0; kk < 64; kk++) {
            float4 pv = *(const float4*)&Pt[kk * 68 + 4 * ty];
            ulonglong2 va = *(const ulonglong2*)&Vs[kk * 68 + 4 * tx];
            ulonglong2 vb = *(const ulonglong2*)&Vs[kk * 68 + 32 + 4 * tx];
            unsigned long long pd[4];
            pd[0] = pack2(pv.x); pd[1] = pack2(pv.y);
            pd[2] = pack2(pv.z); pd[3] = pack2(pv.w);
            #pragma unroll
            for (int i = 0; i < 4; i++) {
                o2[i][0] = fma2(pd[i], va.x, o2[i][0]);
                o2[i][1] = fma2(pd[i], va.y, o2[i][1]);
                o2[i][2] = fma2(pd[i], vb.x, o2[i][2]);
                o2[i][3] = fma2(pd[i], vb.y, o2[i][3]);
            }
        }

        cp_async_wait_all();              // next tile landed
        __syncthreads();                  // all reads of cur buffers + Pt done
        cur ^= 1;
    }

    // epilogue: O /= l; d cols {4tx..+3} and {32+4tx..+3}
    #pragma unroll
    for (int i = 0; i < 4; i++) {
        float inv = 1.f / l[i];
        int n = q0 + 4 * ty + i;
        float2 f0 = unpack2(o2[i][0]);
        float2 f1 = unpack2(o2[i][1]);
        float2 f2 = unpack2(o2[i][2]);
        float2 f3 = unpack2(o2[i][3]);
        float4 oa, ob;
        oa.x = f0.x * inv; oa.y = f0.y * inv; oa.z = f1.x * inv; oa.w = f1.y * inv;
        ob.x = f2.x * inv; ob.y = f2.y * inv; ob.z = f3.x * inv; ob.w = f3.y * inv;
        float* op = &out[n * EDIM + h * HD];
        *(float4*)(op + 4 * tx)      = oa;
        *(float4*)(op + 32 + 4 * tx) = ob;
    }
}

// ---------------------------------------------------------------------------
// Launch.  Inputs (metadata order): x, distance, qkv_w, qkv_b, rpe_table
// ---------------------------------------------------------------------------
extern "C" void kernel_launch(void* const* d_in, const int* in_sizes, int n_in,
                              void* d_out, int out_size)
{
    const float* x    = (const float*)d_in[0];
    const int*   dist = (const int*)  d_in[1];
    const float* w    = (const float*)d_in[2];
    const float* b    = (const float*)d_in[3];
    const float* rpe  = (const float*)d_in[4];
    float*       out  = (float*)d_out;

    // 1) QKV projection (FFMA2)
    qkv_proj_kernel<<<dim3(NTOK / 64, (3 * EDIM) / 64), 256>>>(x, w, b);

    // 2) flash attention: grid (query tiles, heads), 128 threads, 2 CTAs/SM
    const int smem_bytes = (6 * TB + 24) * (int)sizeof(float);  // 104544 B
    cudaFuncSetAttribute(attn_kernel,
                         cudaFuncAttributeMaxDynamicSharedMemorySize, smem_bytes);
    attn_kernel<<<dim3(NTOK / 64, NH), 128, smem_bytes>>>(dist, rpe, out);
}

// round 16
// speedup vs baseline: 1.1364x; 1.1364x over previous
#include <cuda_runtime.h>

#define NTOK 4096
#define EDIM 384
#define NH   6
#define HD   64
#define MAXD 20
#define LOG2E 1.4426950408889634f
#define NSPLIT 3
#define NTILES (NTOK / 64)          // 64 KV tiles total

// Scratch: Q,K stored d-major [h][d][n] (so attention needs no smem transpose);
// V stored token-major [h][n][d].
__device__ float g_Q[NH * HD * NTOK];
__device__ float g_K[NH * HD * NTOK];
__device__ float g_V[NH * NTOK * HD];
// Split-KV partials: unnormalized O and row-sums l per split.
__device__ float g_Opart[NSPLIT * NH * NTOK * HD];
__device__ float g_lpart[NSPLIT * NH * NTOK];

// ---------------------------------------------------------------------------
// Packed fp32x2 helpers (Blackwell FFMA2: 2 fp32 MACs per issue)
// ---------------------------------------------------------------------------
__device__ __forceinline__ unsigned long long pack2(float x) {
    unsigned long long r;
    unsigned int u = __float_as_uint(x);
    asm("mov.b64 %0, {%1, %1};" : "=l"(r) : "r"(u));
    return r;
}
__device__ __forceinline__ unsigned long long fma2(
    unsigned long long a, unsigned long long b, unsigned long long c) {
    unsigned long long d;
    asm("fma.rn.f32x2 %0, %1, %2, %3;" : "=l"(d) : "l"(a), "l"(b), "l"(c));
    return d;
}
__device__ __forceinline__ float2 unpack2(unsigned long long v) {
    unsigned int lo, hi;
    asm("mov.b64 {%0, %1}, %2;" : "=r"(lo), "=r"(hi) : "l"(v));
    return make_float2(__uint_as_float(lo), __uint_as_float(hi));
}
__device__ __forceinline__ float ex2(float x) {
    float r;
    asm("ex2.approx.f32 %0, %1;" : "=f"(r) : "f"(x));
    return r;
}
__device__ __forceinline__ void cp_async16(unsigned int dst_smem, const void* src) {
    asm volatile("cp.async.cg.shared.global [%0], [%1], 16;"
                 :: "r"(dst_smem), "l"(src));
}
__device__ __forceinline__ void cp_async_commit() {
    asm volatile("cp.async.commit_group;" ::: "memory");
}
__device__ __forceinline__ void cp_async_wait_all() {
    asm volatile("cp.async.wait_group 0;" ::: "memory");
}

// ---------------------------------------------------------------------------
// Kernel 1: QKV projection, FFMA2 microkernel.
// C[n,c] = sum_k x[n,k]*w[c,k] + b[c].
// Q,K written [h][d][n] (Q pre-scaled by log2e); V written [h][n][d].
// ---------------------------------------------------------------------------
__global__ __launch_bounds__(256) void qkv_proj_kernel(
    const float* __restrict__ x,
    const float* __restrict__ w,
    const float* __restrict__ b)
{
    __shared__ __align__(16) float Xt[64 * 68];  // [kk][row]
    __shared__ __align__(16) float Wt[64 * 68];  // [kk][col]

    const int tid = threadIdx.x;
    const int tx = tid & 15;
    const int ty = tid >> 4;
    const int r0 = blockIdx.x * 64;
    const int by = blockIdx.y;
    const int c0 = by * 64;
    const int s  = by / NH;              // 0=Q, 1=K, 2=V
    const int h  = by % NH;

    unsigned long long acc2[4][2];       // [row][col-pair]
    #pragma unroll
    for (int i = 0; i < 4; i++) { acc2[i][0] = 0ull; acc2[i][1] = 0ull; }

    for (int k0 = 0; k0 < EDIM; k0 += 64) {
        for (int idx = tid; idx < 4096; idx += 256) {
            int kk = idx & 63;
            int row = idx >> 6;
            Xt[kk * 68 + row] = x[(r0 + row) * EDIM + k0 + kk];
            Wt[kk * 68 + row] = w[(c0 + row) * EDIM + k0 + kk];
        }
        __syncthreads();
        #pragma unroll 8
        for (int kk = 0; kk < 64; kk++) {
            float4 xv = *(const float4*)&Xt[kk * 68 + 4 * ty];
            ulonglong2 wv = *(const ulonglong2*)&Wt[kk * 68 + 4 * tx];
            unsigned long long xd[4];
            xd[0] = pack2(xv.x); xd[1] = pack2(xv.y);
            xd[2] = pack2(xv.z); xd[3] = pack2(xv.w);
            #pragma unroll
            for (int i = 0; i < 4; i++) {
                acc2[i][0] = fma2(xd[i], wv.x, acc2[i][0]);
                acc2[i][1] = fma2(xd[i], wv.y, acc2[i][1]);
            }
        }
        __syncthreads();
    }

    float acc[4][4];
    #pragma unroll
    for (int i = 0; i < 4; i++) {
        float2 f0 = unpack2(acc2[i][0]);
        float2 f1 = unpack2(acc2[i][1]);
        acc[i][0] = f0.x; acc[i][1] = f0.y;
        acc[i][2] = f1.x; acc[i][3] = f1.y;
    }

    float4 bv = *(const float4*)&b[c0 + 4 * tx];
    float bf[4] = {bv.x, bv.y, bv.z, bv.w};

    if (s == 2) {
        #pragma unroll
        for (int i = 0; i < 4; i++) {
            int n = r0 + 4 * ty + i;
            float4 ov;
            ov.x = acc[i][0] + bf[0];
            ov.y = acc[i][1] + bf[1];
            ov.z = acc[i][2] + bf[2];
            ov.w = acc[i][3] + bf[3];
            *(float4*)&g_V[(h * NTOK + n) * HD + 4 * tx] = ov;
        }
    } else {
        float* dst = (s == 0) ? g_Q : g_K;
        float scl  = (s == 0) ? LOG2E : 1.0f;
        #pragma unroll
        for (int j = 0; j < 4; j++) {
            int d = 4 * tx + j;
            float4 ov;
            ov.x = (acc[0][j] + bf[j]) * scl;
            ov.y = (acc[1][j] + bf[j]) * scl;
            ov.z = (acc[2][j] + bf[j]) * scl;
            ov.w = (acc[3][j] + bf[j]) * scl;
            *(float4*)&dst[(h * HD + d) * NTOK + r0 + 4 * ty] = ov;
        }
    }
}

// ---------------------------------------------------------------------------
// Kernel 2: flash attention partial, split-KV x3 (gridDim.z = NSPLIT).
// 64 KV tiles split 22/21/21 across z (4 waves of 1152 CTAs at occ 2 ->
// ~3% wave-quantization waste vs 15% at NSPLIT=2).
// No-max softmax (shift-invariant; scores bounded) -> partials combine
// linearly. FFMA2 microkernel, cp.async double-buffered K/V, warp-private
// Pt (__syncwarp only), ONE __syncthreads per tile.
// 128 threads: tx=tid&7, ty=tid>>3; frag 4 rows x 8 cols
// (cols {4tx..4tx+3} u {32+4tx..35+4tx}).
// smem: Qt | K0 | K1 | V0 | V1 | Pt | bias
// ---------------------------------------------------------------------------
#define TB (64 * 68)

__device__ __forceinline__ void prefetch_tile(
    int h, int j0, int tid, unsigned int kdst, unsigned int vdst)
{
    #pragma unroll
    for (int it = 0; it < 8; it++) {
        int idx = tid + it * 128;
        int a  = idx >> 4;               // d-row for K, token-row for V
        int c4 = (idx & 15) * 4;
        unsigned int soff = (unsigned int)(a * 68 + c4) * 4u;
        cp_async16(kdst + soff, &g_K[(h * HD + a) * NTOK + j0 + c4]);
        cp_async16(vdst + soff, &g_V[(h * NTOK + j0 + a) * HD + c4]);
    }
}

__global__ __launch_bounds__(128, 2) void attn_kernel(
    const int*   __restrict__ dist,
    const float* __restrict__ rpe)
{
    extern __shared__ __align__(16) float smem[];
    float* Qt     = smem;                 // [64][68]  Q^T: [d][row]
    float* Kb     = smem + TB;            // two K^T buffers [d][col]
    float* Vb     = smem + 3 * TB;        // two V buffers [k][d]
    float* Pt     = smem + 5 * TB;        // P^T: [k][row] (warp-private cols)
    float* bias_s = smem + 6 * TB;        // [21]

    const int tid = threadIdx.x;
    const int tx = tid & 7;
    const int ty = tid >> 3;
    const int h  = blockIdx.y;
    const int q0 = blockIdx.x * 64;
    const int z  = blockIdx.z;
    // tiles split 22/21/21: z0 [0,22), z1 [22,43), z2 [43,64)
    const int tbeg = z * (NTILES / NSPLIT) + (z > 0 ? 1 : 0);
    const int tcnt = (NTILES / NSPLIT) + (z == 0 ? 1 : 0);
    const int jbeg = tbeg * 64;
    const int jend = (tbeg + tcnt) * 64;

    const unsigned int smem_u32 = (unsigned int)__cvta_generic_to_shared(smem);
    const unsigned int kbuf_u32[2] = {smem_u32 + 1 * TB * 4, smem_u32 + 2 * TB * 4};
    const unsigned int vbuf_u32[2] = {smem_u32 + 3 * TB * 4, smem_u32 + 4 * TB * 4};

    // start async load of first tile immediately
    prefetch_tile(h, jbeg, tid, kbuf_u32[0], vbuf_u32[0]);
    cp_async_commit();

    if (tid < MAXD + 1) bias_s[tid] = rpe[tid * NH + h] * LOG2E;

    // Q tile: g_Q is [h][d][n] -> direct float4 copy (no transpose)
    for (int idx = tid; idx < 1024; idx += 128) {
        int d  = idx >> 4;
        int c4 = (idx & 15) * 4;
        *(float4*)&Qt[d * 68 + c4] =
            *(const float4*)&g_Q[(h * HD + d) * NTOK + q0 + c4];
    }

    unsigned long long o2[4][4];          // [row][d-pair]
    #pragma unroll
    for (int i = 0; i < 4; i++)
        #pragma unroll
        for (int j = 0; j < 4; j++) o2[i][j] = 0ull;
    float l[4] = {};                      // lane-partial row sums

    cp_async_wait_all();
    __syncthreads();                      // tile 0, Qt, bias_s all visible

    int cur = 0;
    for (int j0 = jbeg; j0 < jend; j0 += 64) {
        // async prefetch of next tile into the alternate buffer
        // (skipped entirely on the final iteration: nothing left to load)
        if (j0 + 64 < jend)
            prefetch_tile(h, j0 + 64, tid, kbuf_u32[cur ^ 1], vbuf_u32[cur ^ 1]);
        cp_async_commit();

        const float* KPt = Kb + cur * TB;
        const float* Vs  = Vb + cur * TB;

        // distance rows: issued now, consumed after the S-GEMM
        int4 drow[4][2];
        #pragma unroll
        for (int i = 0; i < 4; i++) {
            const int* dp = &dist[(q0 + 4 * ty + i) * NTOK + j0];
            drow[i][0] = *(const int4*)(dp + 4 * tx);
            drow[i][1] = *(const int4*)(dp + 32 + 4 * tx);
        }

        // S = (log2e*Q) K^T : packed FFMA2, 64 d-steps
        unsigned long long s2[4][4];
        #pragma unroll
        for (int i = 0; i < 4; i++)
            #pragma unroll
            for (int j = 0; j < 4; j++) s2[i][j] = 0ull;

        #pragma unroll 8
        for (int kk = 0; kk < 64; kk++) {
            float4 qv = *(const float4*)&Qt[kk * 68 + 4 * ty];
            ulonglong2 ka = *(const ulonglong2*)&KPt[kk * 68 + 4 * tx];
            ulonglong2 kb = *(const ulonglong2*)&KPt[kk * 68 + 32 + 4 * tx];
            unsigned long long qd[4];
            qd[0] = pack2(qv.x); qd[1] = pack2(qv.y);
            qd[2] = pack2(qv.z); qd[3] = pack2(qv.w);
            #pragma unroll
            for (int i = 0; i < 4; i++) {
                s2[i][0] = fma2(qd[i], ka.x, s2[i][0]);
                s2[i][1] = fma2(qd[i], ka.y, s2[i][1]);
                s2[i][2] = fma2(qd[i], kb.x, s2[i][2]);
                s2[i][3] = fma2(qd[i], kb.y, s2[i][3]);
            }
        }

        // unpack, bias lookup (upper clamp only; distance >= 0 by spec),
        // p = exp2(s + bias); accumulate lane-partial l. No shuffles.
        float p[4][8];
        #pragma unroll
        for (int i = 0; i < 4; i++) {
            int da[8] = {drow[i][0].x, drow[i][0].y, drow[i][0].z, drow[i][0].w,
                         drow[i][1].x, drow[i][1].y, drow[i][1].z, drow[i][1].w};
            float s[8];
            #pragma unroll
            for (int jc = 0; jc < 4; jc++) {
                float2 f = unpack2(s2[i][jc]);
                s[2 * jc]     = f.x;
                s[2 * jc + 1] = f.y;
            }
            float rs = 0.f;
            #pragma unroll
            for (int j = 0; j < 8; j++) {
                int dc = (da[j] > MAXD) ? MAXD : da[j];
                p[i][j] = ex2(s[j] + bias_s[dc]);
                rs += p[i][j];
            }
            l[i] += rs;
        }

        // write P^T: [k][row]; float4 columns 4ty..4ty+3 are warp-private
        __syncwarp();
        #pragma unroll
        for (int j = 0; j < 8; j++) {
            int k = (j < 4) ? (4 * tx + j) : (32 + 4 * tx + (j - 4));
            float4 pv;
            pv.x = p[0][j]; pv.y = p[1][j]; pv.z = p[2][j]; pv.w = p[3][j];
            *(float4*)&Pt[k * 68 + 4 * ty] = pv;
        }
        __syncwarp();

        // O += P V : packed FFMA2, 64 k-steps
        #pragma unroll 8
        for (int kk = 0; kk < 64; kk++) {
            float4 pv = *(const float4*)&Pt[kk * 68 + 4 * ty];
            ulonglong2 va = *(const ulonglong2*)&Vs[kk * 68 + 4 * tx];
            ulonglong2 vb = *(const ulonglong2*)&Vs[kk * 68 + 32 + 4 * tx];
            unsigned long long pd[4];
            pd[0] = pack2(pv.x); pd[1] = pack2(pv.y);
            pd[2] = pack2(pv.z); pd[3] = pack2(pv.w);
            #pragma unroll
            for (int i = 0; i < 4; i++) {
                o2[i][0] = fma2(pd[i], va.x, o2[i][0]);
                o2[i][1] = fma2(pd[i], va.y, o2[i][1]);
                o2[i][2] = fma2(pd[i], vb.x, o2[i][2]);
                o2[i][3] = fma2(pd[i], vb.y, o2[i][3]);
            }
        }

        cp_async_wait_all();              // next tile landed (or no-op on last)
        __syncthreads();                  // sole CTA barrier: buffer flip
        cur ^= 1;
    }

    // epilogue: reduce lane-partial l ONCE; write UNNORMALIZED O + l to scratch
    #pragma unroll
    for (int i = 0; i < 4; i++) {
        l[i] += __shfl_xor_sync(0xffffffffu, l[i], 1);
        l[i] += __shfl_xor_sync(0xffffffffu, l[i], 2);
        l[i] += __shfl_xor_sync(0xffffffffu, l[i], 4);
    }
    float* obase = &g_Opart[(size_t)(z * NH + h) * NTOK * HD];
    float* lbase = &g_lpart[(size_t)(z * NH + h) * NTOK];
    #pragma unroll
    for (int i = 0; i < 4; i++) {
        int n = q0 + 4 * ty + i;
        float2 f0 = unpack2(o2[i][0]);
        float2 f1 = unpack2(o2[i][1]);
        float2 f2 = unpack2(o2[i][2]);
        float2 f3 = unpack2(o2[i][3]);
        float4 oa = make_float4(f0.x, f0.y, f1.x, f1.y);
        float4 ob = make_float4(f2.x, f2.y, f3.x, f3.y);
        float* op = &obase[(size_t)n * HD];
        *(float4*)(op + 4 * tx)      = oa;
        *(float4*)(op + 32 + 4 * tx) = ob;
        if (tx == 0) lbase[n] = l[i];
    }
}

// ---------------------------------------------------------------------------
// Kernel 3: combine splits.  out[n, h*64+d] = sum_z O_z / sum_z l_z.
// One float4 per thread; NTOK*EDIM/4 threads.
// ---------------------------------------------------------------------------
__global__ __launch_bounds__(256) void combine_kernel(float* __restrict__ out)
{
    int idx = blockIdx.x * 256 + threadIdx.x;      // [0, NTOK*NH*16)
    int d4  = idx & 15;
    int t   = idx >> 4;
    int hh  = t % NH;
    int n   = t / NH;

    const size_t ostride = (size_t)NH * NTOK * HD;
    size_t obase = ((size_t)hh * NTOK + n) * HD + d4 * 4;
    float4 o = make_float4(0.f, 0.f, 0.f, 0.f);
    float lsum = 0.f;
    #pragma unroll
    for (int z = 0; z < NSPLIT; z++) {
        float4 a = *(const float4*)&g_Opart[obase + (size_t)z * ostride];
        o.x += a.x; o.y += a.y; o.z += a.z; o.w += a.w;
        lsum += g_lpart[(size_t)z * NH * NTOK + (size_t)hh * NTOK + n];
    }
    float inv = 1.f / lsum;
    o.x *= inv; o.y *= inv; o.z *= inv; o.w *= inv;
    *(float4*)&out[(size_t)n * EDIM + hh * HD + d4 * 4] = o;
}

// ---------------------------------------------------------------------------
// Launch.  Inputs (metadata order): x, distance, qkv_w, qkv_b, rpe_table
// ---------------------------------------------------------------------------
extern "C" void kernel_launch(void* const* d_in, const int* in_sizes, int n_in,
                              void* d_out, int out_size)
{
    const float* x    = (const float*)d_in[0];
    const int*   dist = (const int*)  d_in[1];
    const float* w    = (const float*)d_in[2];
    const float* b    = (const float*)d_in[3];
    const float* rpe  = (const float*)d_in[4];
    float*       out  = (float*)d_out;

    // 1) QKV projection (FFMA2)
    qkv_proj_kernel<<<dim3(NTOK / 64, (3 * EDIM) / 64), 256>>>(x, w, b);

    // 2) flash attention partials: (query tiles, heads, KV splits)
    const int smem_bytes = (6 * TB + 24) * (int)sizeof(float);  // 104544 B
    cudaFuncSetAttribute(attn_kernel,
                         cudaFuncAttributeMaxDynamicSharedMemorySize, smem_bytes);
    attn_kernel<<<dim3(NTOK / 64, NH, NSPLIT), 128, smem_bytes>>>(dist, rpe);

    // 3) combine splits + normalize
    combine_kernel<<<(NTOK * EDIM / 4) / 256, 256>>>(out);
}